// round 10
// baseline (speedup 1.0000x reference)
#include <cuda_runtime.h>
#include <cuda_fp16.h>
#include <math.h>

#define N_NODES 100000
#define D_FEAT  128
#define NELEM   (N_NODES * D_FEAT)
#define PAD     96      // padded CSR capacity per row (mean deg 32, sigma 5.7)
#define NPAIR   (N_NODES / 2)

// fp16 hop buffers: one uint4 = 8 halves; row = 16 uint4 (256B)
__device__ uint4 g_bufA[NELEM / 8];
__device__ uint4 g_bufB[NELEM / 8];
__device__ uint4 g_Xh[NELEM / 8];                 // fp16 copy of X
__device__ int   g_cnt[N_NODES];                  // fill cursors -> degrees
__device__ int2  g_csr[(size_t)N_NODES * PAD];    // .x = col, .y = half2(v,v) bits

static __forceinline__ __device__ float fguard(float x) {
    return isfinite(x) ? x : 0.0f;
}

static __forceinline__ __device__ unsigned pack_vh2(float v) {
    unsigned h = __half_as_ushort(__float2half_rn(v));
    return h | (h << 16);
}

static __forceinline__ __device__ unsigned pack_h2(float a, float b) {
    __half2 h = __floats2half2_rn(a, b);
    return *(unsigned*)&h;
}

// out = w0 * X ; X -> fp16 uint4 copy ; zero cursors.  i ranges over NELEM/8.
__global__ void init_kernel(const float* __restrict__ X,
                            const float* __restrict__ gw,
                            float* __restrict__ out, int n8) {
    int i = blockIdx.x * blockDim.x + threadIdx.x;
    if (i < N_NODES) g_cnt[i] = 0;
    if (i >= n8) return;
    float w0 = __ldg(gw);
    float4 x0 = ((const float4*)X)[2 * i];
    float4 x1 = ((const float4*)X)[2 * i + 1];
    float4 o0, o1;
    o0.x = w0 * x0.x; o0.y = w0 * x0.y; o0.z = w0 * x0.z; o0.w = w0 * x0.w;
    o1.x = w0 * x1.x; o1.y = w0 * x1.y; o1.z = w0 * x1.z; o1.w = w0 * x1.w;
    ((float4*)out)[2 * i]     = o0;
    ((float4*)out)[2 * i + 1] = o1;
    uint4 u;
    u.x = pack_h2(x0.x, x0.y); u.y = pack_h2(x0.z, x0.w);
    u.z = pack_h2(x1.x, x1.y); u.w = pack_h2(x1.z, x1.w);
    g_Xh[i] = u;
}

// Direct padded-CSR fill: atomic cursor per row, 4 edges per thread.
// Value stored pre-packed as duplicated half2.
__global__ void fill_kernel(const int*   __restrict__ erow,
                            const int*   __restrict__ ecol,
                            const float* __restrict__ evals, int nE) {
    int base = (blockIdx.x * blockDim.x + threadIdx.x) * 4;
    if (base + 3 < nE) {
        int4   r = *(const int4*)(erow + base);
        int4   c = *(const int4*)(ecol + base);
        float4 v = *(const float4*)(evals + base);
        int p0 = atomicAdd(&g_cnt[r.x], 1);
        int p1 = atomicAdd(&g_cnt[r.y], 1);
        int p2 = atomicAdd(&g_cnt[r.z], 1);
        int p3 = atomicAdd(&g_cnt[r.w], 1);
        if (p0 < PAD) g_csr[(size_t)r.x * PAD + p0] = make_int2(c.x, (int)pack_vh2(v.x));
        if (p1 < PAD) g_csr[(size_t)r.y * PAD + p1] = make_int2(c.y, (int)pack_vh2(v.y));
        if (p2 < PAD) g_csr[(size_t)r.z * PAD + p2] = make_int2(c.z, (int)pack_vh2(v.z));
        if (p3 < PAD) g_csr[(size_t)r.w * PAD + p3] = make_int2(c.w, (int)pack_vh2(v.w));
    } else {
        for (int e = base; e < nE; ++e) {
            int r = erow[e];
            int pos = atomicAdd(&g_cnt[r], 1);
            if (pos < PAD) g_csr[(size_t)r * PAD + pos] = make_int2(ecol[e], (int)pack_vh2(evals[e]));
        }
    }
}

// One edge per half-warp per iteration: uniform CSR load + uint4 gather + 4 HFMA2.
#define BODY(J, G)                                                    \
    do {                                                              \
        int2 _e = cp[(J)];                                            \
        unsigned _vb = (unsigned)_e.y;                                \
        if (G) _vb = ((J) < deg) ? _vb : 0u;                          \
        __half2 _v = *(__half2*)&_vb;                                 \
        uint4 _u = H[(size_t)_e.x * 16 + lane16];                     \
        a0 = __hfma2(_v, *(__half2*)&_u.x, a0);                       \
        a1 = __hfma2(_v, *(__half2*)&_u.y, a1);                       \
        a2 = __hfma2(_v, *(__half2*)&_u.z, a2);                       \
        a3 = __hfma2(_v, *(__half2*)&_u.w, a3);                       \
    } while (0)

#define FLUSH()                                                       \
    do {                                                              \
        float2 _t0 = __half22float2(a0), _t1 = __half22float2(a1);    \
        float2 _t2 = __half22float2(a2), _t3 = __half22float2(a3);    \
        f0 += _t0.x; f1 += _t0.y; f2 += _t1.x; f3 += _t1.y;           \
        f4 += _t2.x; f5 += _t2.y; f6 += _t3.x; f7 += _t3.y;           \
        a0 = hz; a1 = hz; a2 = hz; a3 = hz;                           \
    } while (0)

// Gather-SpMM: 2 rows per warp, 16 lanes per row, lane owns 8 features.
// sel: 2 = Xh -> bufA ; 0 = bufA -> bufB ; 1 = bufB -> bufA
__global__ void __launch_bounds__(256, 6) spmm_kernel(const float* __restrict__ gw,
                                                      int l, int sel, int write_h,
                                                      float* __restrict__ out) {
    int w = (blockIdx.x * blockDim.x + threadIdx.x) >> 5;
    if (w >= NPAIR) return;
    int lane = threadIdx.x & 31;
    int lane16 = lane & 15;
    int row = w * 2 + (lane >> 4);

    const uint4* __restrict__ H = (sel == 2) ? g_Xh : (sel == 0 ? g_bufA : g_bufB);
    uint4* __restrict__ Hn = (sel == 0) ? g_bufB : g_bufA;

    int deg = min(g_cnt[row], PAD);
    const int2* __restrict__ cp = g_csr + (size_t)row * PAD;

    int odeg = __shfl_xor_sync(0xffffffffu, deg, 16);
    int dmin = min(deg, odeg);
    int dmax = max(deg, odeg);

    float f0 = 0.f, f1 = 0.f, f2 = 0.f, f3 = 0.f;
    float f4 = 0.f, f5 = 0.f, f6 = 0.f, f7 = 0.f;
    const __half2 hz = __floats2half2_rn(0.f, 0.f);
    __half2 a0 = hz, a1 = hz, a2 = hz, a3 = hz;

    int j = 0;
    // fast path: 16-edge groups (both halves full), unroll-4 for MLP
    for (; j + 16 <= dmin; j += 16) {
        #pragma unroll 4
        for (int t = 0; t < 16; ++t) BODY(j + t, 0);
        FLUSH();
    }
    // remaining common part
    int cnt = 0;
    for (; j < dmin; ++j) {
        BODY(j, 0);
        if (++cnt == 16) { FLUSH(); cnt = 0; }
    }
    // imbalanced tail: guard own degree (stale CSR cols are valid node ids)
    for (; j < dmax; ++j) {
        BODY(j, 1);
        if (++cnt == 16) { FLUSH(); cnt = 0; }
    }
    FLUSH();

    f0 = fguard(f0); f1 = fguard(f1); f2 = fguard(f2); f3 = fguard(f3);
    f4 = fguard(f4); f5 = fguard(f5); f6 = fguard(f6); f7 = fguard(f7);

    if (write_h) {
        uint4 s;
        s.x = pack_h2(f0, f1); s.y = pack_h2(f2, f3);
        s.z = pack_h2(f4, f5); s.w = pack_h2(f6, f7);
        Hn[(size_t)row * 16 + lane16] = s;
    }

    float wl = __ldg(gw + l);
    float4* op = (float4*)out + (size_t)row * 32 + lane16 * 2;
    float4 o = op[0];
    o.x = fmaf(wl, f0, o.x); o.y = fmaf(wl, f1, o.y);
    o.z = fmaf(wl, f2, o.z); o.w = fmaf(wl, f3, o.w);
    op[0] = o;
    o = op[1];
    o.x = fmaf(wl, f4, o.x); o.y = fmaf(wl, f5, o.y);
    o.z = fmaf(wl, f6, o.z); o.w = fmaf(wl, f7, o.w);
    op[1] = o;
}

extern "C" void kernel_launch(void* const* d_in, const int* in_sizes, int n_in,
                              void* d_out, int out_size) {
    const int*   erow  = (const int*)  d_in[0];
    const int*   ecol  = (const int*)  d_in[1];
    const float* evals = (const float*)d_in[2];
    const float* X     = (const float*)d_in[3];
    const float* gw    = (const float*)d_in[4];
    float* out = (float*)d_out;

    int nE = in_sizes[0];
    int n8 = in_sizes[3] / 8;                        // 1.6M uint4 rows-of-8
    int init_blocks  = (n8 + 255) / 256;
    int edge4_blocks = ((nE + 3) / 4 + 255) / 256;
    int spmm_blocks  = (NPAIR * 32 + 255) / 256;     // one warp per row pair

    init_kernel<<<init_blocks, 256>>>(X, gw, out, n8);
    fill_kernel<<<edge4_blocks, 256>>>(erow, ecol, evals, nE);

    for (int l = 1; l <= 10; ++l) {
        int sel = (l == 1) ? 2 : ((l & 1) ? 1 : 0);  // even hops read A, odd (>=3) read B
        spmm_kernel<<<spmm_blocks, 256>>>(gw, l, sel, (l < 10) ? 1 : 0, out);
    }
}

// round 11
// speedup vs baseline: 1.1710x; 1.1710x over previous
#include <cuda_runtime.h>
#include <cuda_fp16.h>
#include <math.h>

#define N_NODES 100000
#define D_FEAT  128
#define NELEM   (N_NODES * D_FEAT)
#define PAD     96      // padded CSR capacity per row (mean deg 32, sigma 5.7)
#define NW4     (NELEM / 4)

// fp16 buffers: one uint2 = 4 halves; row = 32 uint2 (256B)
__device__ uint2 g_Xh[NW4];                       // fp16 copy of X
__device__ uint2 g_H[9][NW4];                     // H_1 .. H_9 (fp16)
__device__ int   g_cnt[N_NODES];                  // fill cursors -> degrees
__device__ int2  g_csr[(size_t)N_NODES * PAD];    // .x = col, .y = f32 val bits

static __forceinline__ __device__ float fguard(float x) {
    return isfinite(x) ? x : 0.0f;
}

// X -> fp16 copy ; zero cursors. (out is written by the fused hop-10 kernel.)
__global__ void init_kernel(const float* __restrict__ X, int n4) {
    int i = blockIdx.x * blockDim.x + threadIdx.x;
    if (i < N_NODES) g_cnt[i] = 0;
    if (i >= n4) return;
    float4 x = ((const float4*)X)[i];
    __half2 h0 = __floats2half2_rn(x.x, x.y);
    __half2 h1 = __floats2half2_rn(x.z, x.w);
    uint2 u;
    u.x = *(unsigned*)&h0; u.y = *(unsigned*)&h1;
    g_Xh[i] = u;
}

// Direct padded-CSR fill: atomic cursor per row, 4 edges per thread.
__global__ void fill_kernel(const int*   __restrict__ erow,
                            const int*   __restrict__ ecol,
                            const float* __restrict__ evals, int nE) {
    int base = (blockIdx.x * blockDim.x + threadIdx.x) * 4;
    if (base + 3 < nE) {
        int4   r = *(const int4*)(erow + base);
        int4   c = *(const int4*)(ecol + base);
        float4 v = *(const float4*)(evals + base);
        int p0 = atomicAdd(&g_cnt[r.x], 1);
        int p1 = atomicAdd(&g_cnt[r.y], 1);
        int p2 = atomicAdd(&g_cnt[r.z], 1);
        int p3 = atomicAdd(&g_cnt[r.w], 1);
        if (p0 < PAD) g_csr[(size_t)r.x * PAD + p0] = make_int2(c.x, __float_as_int(v.x));
        if (p1 < PAD) g_csr[(size_t)r.y * PAD + p1] = make_int2(c.y, __float_as_int(v.y));
        if (p2 < PAD) g_csr[(size_t)r.z * PAD + p2] = make_int2(c.z, __float_as_int(v.z));
        if (p3 < PAD) g_csr[(size_t)r.w * PAD + p3] = make_int2(c.w, __float_as_int(v.w));
    } else {
        for (int e = base; e < nE; ++e) {
            int r = erow[e];
            int pos = atomicAdd(&g_cnt[r], 1);
            if (pos < PAD) g_csr[(size_t)r * PAD + pos] = make_int2(ecol[e], __float_as_int(evals[e]));
        }
    }
}

// R6's proven edge body: batch-load CSR + shfl broadcast + fp32 FMA.
#define EDGE_BODY(EDX, EDY)                                           \
    do {                                                              \
        int   _c = __shfl_sync(0xffffffffu, (EDX), j);                \
        float _v = __int_as_float(__shfl_sync(0xffffffffu, (EDY), j));\
        uint2 _u = H[(size_t)_c * 32 + lane];                         \
        float2 _f0 = __half22float2(*(__half2*)&_u.x);                \
        float2 _f1 = __half22float2(*(__half2*)&_u.y);                \
        acc.x = fmaf(_v, _f0.x, acc.x);                               \
        acc.y = fmaf(_v, _f0.y, acc.y);                               \
        acc.z = fmaf(_v, _f1.x, acc.z);                               \
        acc.w = fmaf(_v, _f1.y, acc.w);                               \
    } while (0)

#define SPMM_LOOP()                                                   \
    float4 acc = make_float4(0.f, 0.f, 0.f, 0.f);                     \
    {                                                                 \
        int base = 0;                                                 \
        for (; base + 32 <= deg; base += 32) {                        \
            int2 ed = cp[base + lane];                                \
            _Pragma("unroll")                                         \
            for (int j = 0; j < 32; ++j) EDGE_BODY(ed.x, ed.y);       \
        }                                                             \
        int rem = deg - base;                                         \
        if (rem > 0) {                                                \
            int2 ed = (lane < rem) ? cp[base + lane] : make_int2(0, 0);\
            _Pragma("unroll 8")                                       \
            for (int j = 0; j < rem; ++j) EDGE_BODY(ed.x, ed.y);      \
        }                                                             \
    }                                                                 \
    acc.x = fguard(acc.x); acc.y = fguard(acc.y);                     \
    acc.z = fguard(acc.z); acc.w = fguard(acc.w);

// Hops 1..9: gather-SpMM, write fp16 H only (no out traffic).
// src: -1 = Xh, else g_H[src]. dst: g_H[dst].
__global__ void __launch_bounds__(256) spmm_kernel(int src, int dst) {
    int w = (blockIdx.x * blockDim.x + threadIdx.x) >> 5;
    if (w >= N_NODES) return;
    int lane = threadIdx.x & 31;

    const uint2* __restrict__ H = (src < 0) ? g_Xh : g_H[src];

    int deg = min(g_cnt[w], PAD);
    const int2* __restrict__ cp = g_csr + (size_t)w * PAD;

    SPMM_LOOP();

    __half2 o0 = __floats2half2_rn(acc.x, acc.y);
    __half2 o1 = __floats2half2_rn(acc.z, acc.w);
    uint2 u;
    u.x = *(unsigned*)&o0; u.y = *(unsigned*)&o1;
    g_H[dst][(size_t)w * 32 + lane] = u;
}

// Hop 10 fused with the final reduction:
// acc = H_10 (registers); out = w0*X + sum_{l=1..9} w_l*H_l + w10*acc.
__global__ void __launch_bounds__(256) spmm_final_kernel(const float* __restrict__ X,
                                                         const float* __restrict__ gw,
                                                         float* __restrict__ out) {
    int w = (blockIdx.x * blockDim.x + threadIdx.x) >> 5;
    if (w >= N_NODES) return;
    int lane = threadIdx.x & 31;

    const uint2* __restrict__ H = g_H[8];   // H_9

    int deg = min(g_cnt[w], PAD);
    const int2* __restrict__ cp = g_csr + (size_t)w * PAD;

    SPMM_LOOP();

    size_t idx = (size_t)w * 32 + lane;
    float4 x = ((const float4*)X)[idx];
    float w0 = __ldg(gw);
    float4 o;
    o.x = w0 * x.x; o.y = w0 * x.y; o.z = w0 * x.z; o.w = w0 * x.w;

    #pragma unroll
    for (int k = 0; k < 9; ++k) {
        float wl = __ldg(gw + k + 1);
        uint2 u = g_H[k][idx];
        float2 f0 = __half22float2(*(__half2*)&u.x);
        float2 f1 = __half22float2(*(__half2*)&u.y);
        o.x = fmaf(wl, f0.x, o.x);
        o.y = fmaf(wl, f0.y, o.y);
        o.z = fmaf(wl, f1.x, o.z);
        o.w = fmaf(wl, f1.y, o.w);
    }

    float w10 = __ldg(gw + 10);
    o.x = fmaf(w10, acc.x, o.x);
    o.y = fmaf(w10, acc.y, o.y);
    o.z = fmaf(w10, acc.z, o.z);
    o.w = fmaf(w10, acc.w, o.w);

    ((float4*)out)[idx] = o;
}

extern "C" void kernel_launch(void* const* d_in, const int* in_sizes, int n_in,
                              void* d_out, int out_size) {
    const int*   erow  = (const int*)  d_in[0];
    const int*   ecol  = (const int*)  d_in[1];
    const float* evals = (const float*)d_in[2];
    const float* X     = (const float*)d_in[3];
    const float* gw    = (const float*)d_in[4];
    float* out = (float*)d_out;

    int nE = in_sizes[0];
    int n4 = in_sizes[3] / 4;
    int init_blocks  = (n4 + 255) / 256;
    int edge4_blocks = ((nE + 3) / 4 + 255) / 256;
    int spmm_blocks  = (N_NODES * 32 + 255) / 256;

    init_kernel<<<init_blocks, 256>>>(X, n4);
    fill_kernel<<<edge4_blocks, 256>>>(erow, ecol, evals, nE);

    // hops 1..9: H_l = A * H_{l-1}, fp16 in/out, no out traffic
    spmm_kernel<<<spmm_blocks, 256>>>(-1, 0);          // hop 1: Xh -> H[0]
    for (int l = 2; l <= 9; ++l)
        spmm_kernel<<<spmm_blocks, 256>>>(l - 2, l - 1);
    // hop 10 fused with full out reduction
    spmm_final_kernel<<<spmm_blocks, 256>>>(X, gw, out);
}